// round 7
// baseline (speedup 1.0000x reference)
#include <cuda_runtime.h>
#include <cuda_bf16.h>

// StandardDeviationPooling: 4x4 window, stride 2, VALID.
// Input:  [64, 1024, 1024, 1] fp32   Output: [64, 511*511] fp32
// std = sqrt(max(E[x^2] - E[x]^2, 0)) per window.
//
// R7: R6 (shuffle-deduped loads: ONE float4 per thread per input row, zero
// overlap; warp-boundary pair-sums via tiny double-buffered smem slot;
// 32 regs / full occupancy) with ROWS_PER_THREAD 8 -> 16: halves the
// strip-boundary re-read overlap (2 of 34 rows vs 2 of 18) and the
// __syncthreads count. DRAM traffic is already within 1.5% of the 323 MB
// floor at the 5.97 TB/s mixed-stream plateau; this chases the residual.

#define H_IN 1024
#define W_IN 1024
#define H_OUT 511
#define W_OUT 511
#define ROWS_PER_THREAD 16

__global__ __launch_bounds__(256, 8)
void std_pool_kernel(const float* __restrict__ in, float* __restrict__ out) {
    __shared__ float2 xch[2][8];   // [j parity][warp] : lane0's (own01, oq01)

    const int c      = threadIdx.x;          // col-pair index 0..255
    const int lane   = c & 31;
    const int warpid = c >> 5;               // 0..7
    const int r0     = blockIdx.y * ROWS_PER_THREAD;
    const int b      = blockIdx.z;

    const float* __restrict__ inb  = in  + (size_t)b * H_IN * W_IN;
    float* __restrict__       outb = out + (size_t)b * H_OUT * W_OUT;

    const int  ic     = 4 * c;               // own float4: cols 4c..4c+3
    const int  oc0    = 2 * c;
    const int  nwarp  = (warpid < 7) ? warpid + 1 : 7;  // clamped (w7 lane31 unused)
    const float inv_n = 1.0f / 16.0f;

    // previous row-pair sums/sumsq for the 2 output cols
    float ps0 = 0.f, ps1 = 0.f, pq0 = 0.f, pq1 = 0.f;

    #pragma unroll
    for (int j = 0; j <= ROWS_PER_THREAD; ++j) {
        const int irow = 2 * (r0 + j);

        // own row-pair partials: cols (4c,4c+1) and (4c+2,4c+3)
        float own01 = 0.f, own23 = 0.f, oq01 = 0.f, oq23 = 0.f;

        if (irow + 1 < H_IN) {               // block-uniform guard
            const float* rowp = inb + (size_t)irow * W_IN + ic;
            const float4 a0 = *reinterpret_cast<const float4*>(rowp);
            const float4 a1 = *reinterpret_cast<const float4*>(rowp + W_IN);

            own01 = (a0.x + a0.y) + (a1.x + a1.y);
            own23 = (a0.z + a0.w) + (a1.z + a1.w);
            oq01  = fmaf(a0.x, a0.x, fmaf(a0.y, a0.y,
                    fmaf(a1.x, a1.x, a1.y * a1.y)));
            oq23  = fmaf(a0.z, a0.z, fmaf(a0.w, a0.w,
                    fmaf(a1.z, a1.z, a1.w * a1.w)));
        }

        // publish lane0's left pair to the previous warp's lane 31
        if (lane == 0) xch[j & 1][warpid] = make_float2(own01, oq01);
        __syncthreads();

        // neighbor's (4c+4,4c+5) row-pair partials from lane+1 (or next warp's lane0)
        float n01  = __shfl_down_sync(0xffffffffu, own01, 1);
        float nq01 = __shfl_down_sync(0xffffffffu, oq01, 1);
        if (lane == 31) {
            const float2 t = xch[j & 1][nwarp];
            n01 = t.x; nq01 = t.y;
        }

        const float cs0 = own01 + own23;
        const float cs1 = own23 + n01;
        const float cq0 = oq01 + oq23;
        const float cq1 = oq23 + nq01;

        if (j > 0) {
            const int orow = r0 + j - 1;
            if (orow < H_OUT) {
                float* orow_p = outb + (size_t)orow * W_OUT;
                {
                    const float s = ps0 + cs0, q = pq0 + cq0;
                    const float m = s * inv_n;
                    __stcs(orow_p + oc0, sqrtf(fmaxf(fmaf(-m, m, q * inv_n), 0.f)));
                }
                if (oc0 + 1 < W_OUT) {
                    const float s = ps1 + cs1, q = pq1 + cq1;
                    const float m = s * inv_n;
                    __stcs(orow_p + oc0 + 1, sqrtf(fmaxf(fmaf(-m, m, q * inv_n), 0.f)));
                }
            }
        }
        ps0 = cs0; ps1 = cs1; pq0 = cq0; pq1 = cq1;
    }
}

extern "C" void kernel_launch(void* const* d_in, const int* in_sizes, int n_in,
                              void* d_out, int out_size) {
    const float* in = (const float*)d_in[0];
    float* out = (float*)d_out;
    (void)in_sizes; (void)n_in; (void)out_size;

    // 256 col-pair threads cover 511 output cols; 32 strips of 16 rows; 64 batches.
    dim3 block(256, 1, 1);
    dim3 grid(1, (H_OUT + ROWS_PER_THREAD - 1) / ROWS_PER_THREAD, 64);
    std_pool_kernel<<<grid, block>>>(in, out);
}

// round 8
// speedup vs baseline: 1.0210x; 1.0210x over previous
#include <cuda_runtime.h>
#include <cuda_bf16.h>

// StandardDeviationPooling: 4x4 window, stride 2, VALID.
// Input:  [64, 1024, 1024, 1] fp32   Output: [64, 511*511] fp32
// std = sqrt(max(E[x^2] - E[x]^2, 0)) per window.
//
// R8: chunked row-pairs. Dense shuffle-deduped loads (ONE float4 per thread
// per input row, warp = 512B contiguous, zero overlap) but TWO row-pairs per
// __syncthreads: 4 independent LDG.128 batched per chunk (MLP_p1=4, was 2),
// barriers per thread 17 -> 8. Warp-boundary pair-sums via double-buffered
// smem slots. RPT=15 (16 pair sums = 8 chunks), 35 strips, grid 2240.

#define H_IN 1024
#define W_IN 1024
#define H_OUT 511
#define W_OUT 511
#define ROWS_PER_THREAD 15
#define NCHUNK 8

__global__ __launch_bounds__(256, 6)
void std_pool_kernel(const float* __restrict__ in, float* __restrict__ out) {
    __shared__ float2 xchA[2][8];   // [chunk parity][warp] : lane0 pair-A (s01,q01)
    __shared__ float2 xchB[2][8];   // [chunk parity][warp] : lane0 pair-B (s01,q01)

    const int c      = threadIdx.x;          // col-pair index 0..255
    const int lane   = c & 31;
    const int warpid = c >> 5;               // 0..7
    const int r0     = blockIdx.y * ROWS_PER_THREAD;
    const int b      = blockIdx.z;

    const float* __restrict__ inb  = in  + (size_t)b * H_IN * W_IN;
    float* __restrict__       outb = out + (size_t)b * H_OUT * W_OUT;

    const int  ic     = 4 * c;               // own float4: cols 4c..4c+3
    const int  oc0    = 2 * c;
    const int  nwarp  = (warpid < 7) ? warpid + 1 : 7;  // clamped (w7 lane31 unused)
    const float inv_n = 1.0f / 16.0f;

    // previous row-pair sums/sumsq for the 2 output cols
    float ps0 = 0.f, ps1 = 0.f, pq0 = 0.f, pq1 = 0.f;

    for (int k = 0; k < NCHUNK; ++k) {
        const int irowA = 2 * (r0 + 2 * k);  // pair A: input rows irowA, irowA+1
        const int irowB = irowA + 2;         // pair B: input rows irowB, irowB+1

        float A01 = 0.f, A23 = 0.f, AQ01 = 0.f, AQ23 = 0.f;
        float B01 = 0.f, B23 = 0.f, BQ01 = 0.f, BQ23 = 0.f;

        if (irowB + 1 < H_IN) {
            // common case: all 4 rows in bounds -> 4 batched LDG.128
            const float* rowp = inb + (size_t)irowA * W_IN + ic;
            const float4 a0 = *reinterpret_cast<const float4*>(rowp);
            const float4 a1 = *reinterpret_cast<const float4*>(rowp + W_IN);
            const float4 b0 = *reinterpret_cast<const float4*>(rowp + 2 * W_IN);
            const float4 b1 = *reinterpret_cast<const float4*>(rowp + 3 * W_IN);

            A01  = (a0.x + a0.y) + (a1.x + a1.y);
            A23  = (a0.z + a0.w) + (a1.z + a1.w);
            AQ01 = fmaf(a0.x, a0.x, fmaf(a0.y, a0.y, fmaf(a1.x, a1.x, a1.y * a1.y)));
            AQ23 = fmaf(a0.z, a0.z, fmaf(a0.w, a0.w, fmaf(a1.z, a1.z, a1.w * a1.w)));

            B01  = (b0.x + b0.y) + (b1.x + b1.y);
            B23  = (b0.z + b0.w) + (b1.z + b1.w);
            BQ01 = fmaf(b0.x, b0.x, fmaf(b0.y, b0.y, fmaf(b1.x, b1.x, b1.y * b1.y)));
            BQ23 = fmaf(b0.z, b0.z, fmaf(b0.w, b0.w, fmaf(b1.z, b1.z, b1.w * b1.w)));
        } else if (irowA + 1 < H_IN) {
            // tail strip: only pair A in bounds
            const float* rowp = inb + (size_t)irowA * W_IN + ic;
            const float4 a0 = *reinterpret_cast<const float4*>(rowp);
            const float4 a1 = *reinterpret_cast<const float4*>(rowp + W_IN);
            A01  = (a0.x + a0.y) + (a1.x + a1.y);
            A23  = (a0.z + a0.w) + (a1.z + a1.w);
            AQ01 = fmaf(a0.x, a0.x, fmaf(a0.y, a0.y, fmaf(a1.x, a1.x, a1.y * a1.y)));
            AQ23 = fmaf(a0.z, a0.z, fmaf(a0.w, a0.w, fmaf(a1.z, a1.z, a1.w * a1.w)));
        }

        // publish lane0's left pairs to the previous warp's lane 31
        if (lane == 0) {
            xchA[k & 1][warpid] = make_float2(A01, AQ01);
            xchB[k & 1][warpid] = make_float2(B01, BQ01);
        }
        __syncthreads();

        // neighbor's (4c+4,4c+5) partials from lane+1 (or next warp's lane0)
        float nA01  = __shfl_down_sync(0xffffffffu, A01, 1);
        float nAQ01 = __shfl_down_sync(0xffffffffu, AQ01, 1);
        float nB01  = __shfl_down_sync(0xffffffffu, B01, 1);
        float nBQ01 = __shfl_down_sync(0xffffffffu, BQ01, 1);
        if (lane == 31) {
            const float2 tA = xchA[k & 1][nwarp];
            const float2 tB = xchB[k & 1][nwarp];
            nA01 = tA.x; nAQ01 = tA.y;
            nB01 = tB.x; nBQ01 = tB.y;
        }

        const float csA0 = A01 + A23,   csA1 = A23 + nA01;
        const float cqA0 = AQ01 + AQ23, cqA1 = AQ23 + nAQ01;
        const float csB0 = B01 + B23,   csB1 = B23 + nB01;
        const float cqB0 = BQ01 + BQ23, cqB1 = BQ23 + nBQ01;

        // output row r0 + 2k - 1 : prev pair + pair A   (skip at k==0)
        if (k > 0) {
            const int orow = r0 + 2 * k - 1;
            if (orow < H_OUT) {
                float* orow_p = outb + (size_t)orow * W_OUT;
                {
                    const float s = ps0 + csA0, q = pq0 + cqA0;
                    const float m = s * inv_n;
                    __stcs(orow_p + oc0, sqrtf(fmaxf(fmaf(-m, m, q * inv_n), 0.f)));
                }
                if (oc0 + 1 < W_OUT) {
                    const float s = ps1 + csA1, q = pq1 + cqA1;
                    const float m = s * inv_n;
                    __stcs(orow_p + oc0 + 1, sqrtf(fmaxf(fmaf(-m, m, q * inv_n), 0.f)));
                }
            }
        }

        // output row r0 + 2k : pair A + pair B
        {
            const int orow = r0 + 2 * k;
            if (orow < H_OUT) {
                float* orow_p = outb + (size_t)orow * W_OUT;
                {
                    const float s = csA0 + csB0, q = cqA0 + cqB0;
                    const float m = s * inv_n;
                    __stcs(orow_p + oc0, sqrtf(fmaxf(fmaf(-m, m, q * inv_n), 0.f)));
                }
                if (oc0 + 1 < W_OUT) {
                    const float s = csA1 + csB1, q = cqA1 + cqB1;
                    const float m = s * inv_n;
                    __stcs(orow_p + oc0 + 1, sqrtf(fmaxf(fmaf(-m, m, q * inv_n), 0.f)));
                }
            }
        }

        ps0 = csB0; ps1 = csB1; pq0 = cqB0; pq1 = cqB1;
    }
}

extern "C" void kernel_launch(void* const* d_in, const int* in_sizes, int n_in,
                              void* d_out, int out_size) {
    const float* in = (const float*)d_in[0];
    float* out = (float*)d_out;
    (void)in_sizes; (void)n_in; (void)out_size;

    // 256 col-pair threads cover 511 output cols; 35 strips of 15 rows; 64 batches.
    dim3 block(256, 1, 1);
    dim3 grid(1, (H_OUT + ROWS_PER_THREAD - 1) / ROWS_PER_THREAD, 64);
    std_pool_kernel<<<grid, block>>>(in, out);
}